// round 2
// baseline (speedup 1.0000x reference)
#include <cuda_runtime.h>
#include <math.h>

#define NUM_CLASSES 15
#define NCH 20          // NUM_CLASSES + 5
#define NG 52
#define NA 3
#define PLANE (NG*NG)   // 2704

struct Meta {
    int gi, gj, best, gcls;
    float tx, ty, tw, th;
    int ign0, ign1, ign2;
    int pad;
};

__device__ double g_loss;
__device__ Meta g_meta[1024];

// ---------------------------------------------------------------------------
// K1: per-batch target metadata + zero the loss accumulator
// ---------------------------------------------------------------------------
__global__ void k1_prep(const float* __restrict__ labels, int nB) {
    int b = blockIdx.x * blockDim.x + threadIdx.x;
    if (b == 0) g_loss = 0.0;
    if (b >= nB) return;

    float bx = labels[b*5+0] * (float)NG;
    float by = labels[b*5+1] * (float)NG;
    float bw = labels[b*5+2] * (float)NG;
    float bh = labels[b*5+3] * (float)NG;
    int gi = (int)bx;
    int gj = (int)by;

    // GRID_ANCHOR = [[96/8,230/8],[79/8,186/8],[81/8,133/8]]
    const float aw[3] = {12.0f, 9.875f, 10.125f};
    const float ah[3] = {28.75f, 23.25f, 16.625f};

    float iou[3];
#pragma unroll
    for (int a = 0; a < 3; a++) {
        float inter = fminf(aw[a], bw) * fminf(ah[a], bh);
        iou[a] = inter / (aw[a]*ah[a] + 1e-16f + bw*bh - inter);
    }
    int best = 0;
    if (iou[1] > iou[best]) best = 1;
    if (iou[2] > iou[best]) best = 2;

    Meta m;
    m.gi = gi; m.gj = gj; m.best = best;
    m.gcls = (int)labels[b*5+4];
    m.tx = bx - (float)gi;
    m.ty = by - (float)gj;
    m.tw = logf(bw / aw[best] + 1e-16f);
    m.th = logf(bh / ah[best] + 1e-16f);
    m.ign0 = (iou[0] > 0.5f) ? 1 : 0;
    m.ign1 = (iou[1] > 0.5f) ? 1 : 0;
    m.ign2 = (iou[2] > 0.5f) ? 1 : 0;
    m.pad = 0;
    g_meta[b] = m;
}

// ---------------------------------------------------------------------------
// K2: fused elementwise transform + output write + loss reduction
// One thread per (b, anchor, j, i) cell.
// ---------------------------------------------------------------------------
__global__ __launch_bounds__(256) void k2_main(
    const float* __restrict__ x, float* __restrict__ out, int nB)
{
    int idx = blockIdx.x * blockDim.x + threadIdx.x;
    int total = nB * NA * PLANE;
    float loss = 0.0f;

    if (idx < total) {
        int i = idx % NG;
        int j = (idx / NG) % NG;
        int a = (idx / PLANE) % NA;
        int b = idx / (NA * PLANE);

        const float* base = x + ((size_t)(b * (NA*NCH) + a * NCH)) * PLANE + j * NG + i;

        float ch[NCH];
#pragma unroll
        for (int c = 0; c < NCH; c++)
            ch[c] = base[(size_t)c * PLANE];

        float px   = 1.0f / (1.0f + expf(-ch[0]));
        float py   = 1.0f / (1.0f + expf(-ch[1]));
        float pw   = ch[2];
        float ph   = ch[3];
        float conf = 1.0f / (1.0f + expf(-ch[4]));

        // softmax over ch[5..19]
        float mx = ch[5];
#pragma unroll
        for (int c = 6; c < NCH; c++) mx = fmaxf(mx, ch[c]);
        float s = 0.0f;
#pragma unroll
        for (int c = 5; c < NCH; c++) { ch[c] = expf(ch[c] - mx); s += ch[c]; }
        float inv = 1.0f / s;
#pragma unroll
        for (int c = 5; c < NCH; c++) ch[c] *= inv;

        // output: d_out[0] = loss, then out[b, pos, 20] with pos == idx order
        size_t ob = 1 + (size_t)idx * NCH;
        out[ob + 0] = px * 8.0f;
        out[ob + 1] = py * 8.0f;
        out[ob + 2] = pw * 8.0f;
        out[ob + 3] = ph * 8.0f;
        out[ob + 4] = conf;
#pragma unroll
        for (int c = 5; c < NCH; c++) out[ob + c] = ch[c];

        // ---- loss contributions ----
        Meta mt = g_meta[b];
        bool at_cell = (j == mt.gj) && (i == mt.gi);

        float noobj = 1.0f;
        if (at_cell) {
            int ign = (a == 0) ? mt.ign0 : ((a == 1) ? mt.ign1 : mt.ign2);
            if (a == mt.best || ign) noobj = 0.0f;
        }
        if (noobj != 0.0f)
            loss += 100.0f * (-fmaxf(logf(1.0f - conf), -100.0f));

        if (at_cell && a == mt.best) {
            loss += fabsf(px - mt.tx) + fabsf(py - mt.ty)
                  + fabsf(pw - mt.tw) + fabsf(ph - mt.th);
            loss += -fmaxf(logf(conf), -100.0f);
#pragma unroll
            for (int c = 0; c < NUM_CLASSES; c++) {
                float p = ch[5 + c];
                if (c == mt.gcls) loss += -fmaxf(logf(p), -100.0f);
                else              loss += -fmaxf(logf(1.0f - p), -100.0f);
            }
        }
    }

    // ---- block reduction -> one double atomic per block ----
    __shared__ float warpsum[8];
#pragma unroll
    for (int o = 16; o > 0; o >>= 1)
        loss += __shfl_down_sync(0xffffffffu, loss, o);
    if ((threadIdx.x & 31) == 0) warpsum[threadIdx.x >> 5] = loss;
    __syncthreads();
    if (threadIdx.x < 8) {
        float v = warpsum[threadIdx.x];
#pragma unroll
        for (int o = 4; o > 0; o >>= 1)
            v += __shfl_down_sync(0xffu, v, o);
        if (threadIdx.x == 0)
            atomicAdd(&g_loss, (double)v);
    }
}

// ---------------------------------------------------------------------------
// K3: finalize loss into d_out[0]
// ---------------------------------------------------------------------------
__global__ void k3_final(float* __restrict__ out) {
    out[0] = (float)g_loss;
}

extern "C" void kernel_launch(void* const* d_in, const int* in_sizes, int n_in,
                              void* d_out, int out_size) {
    const float* x      = (const float*)d_in[0];
    const float* labels = (const float*)d_in[1];
    float* out = (float*)d_out;

    int nB = in_sizes[0] / (NA * NCH * PLANE);
    int total = nB * NA * PLANE;

    k1_prep<<<(nB + 127) / 128, 128>>>(labels, nB);
    k2_main<<<(total + 255) / 256, 256>>>(x, out, nB);
    k3_final<<<1, 1>>>(out);
}

// round 3
// speedup vs baseline: 2.6340x; 2.6340x over previous
#include <cuda_runtime.h>
#include <math.h>

#define NUM_CLASSES 15
#define NCH 20          // NUM_CLASSES + 5
#define NG 52
#define NA 3
#define PLANE (NG*NG)   // 2704
#define TPB 256
#define SPAD 21         // padded smem stride (coprime with 32)

__device__ double g_loss;   // zero-initialized at module load; k3 resets after use

// ---------------------------------------------------------------------------
// K2: fused transform + smem-staged coalesced output + loss reduction
// One thread per (b, anchor, j, i) cell; block = 256 cells.
// ---------------------------------------------------------------------------
__global__ __launch_bounds__(TPB) void k2_main(
    const float* __restrict__ x, const float* __restrict__ labels,
    float* __restrict__ out, int nB)
{
    __shared__ float sbuf[TPB * SPAD];

    const int tid  = threadIdx.x;
    const int base = blockIdx.x * TPB;
    const int idx  = base + tid;
    const int total = nB * NA * PLANE;
    float loss = 0.0f;

    if (idx < total) {
        int i = idx % NG;
        int j = (idx / NG) % NG;
        int a = (idx / PLANE) % NA;
        int b = idx / (NA * PLANE);

        const float* xb = x + ((size_t)(b * (NA*NCH) + a * NCH)) * PLANE + j * NG + i;

        float ch[NCH];
#pragma unroll
        for (int c = 0; c < NCH; c++)
            ch[c] = xb[(size_t)c * PLANE];

        // ---- per-thread target meta (broadcast loads, cheap ALU) ----
        float bx = labels[b*5+0] * (float)NG;
        float by = labels[b*5+1] * (float)NG;
        float bw = labels[b*5+2] * (float)NG;
        float bh = labels[b*5+3] * (float)NG;
        int   gcls = (int)labels[b*5+4];
        int   gi = (int)bx;
        int   gj = (int)by;

        const float aw[3] = {12.0f, 9.875f, 10.125f};
        const float ah[3] = {28.75f, 23.25f, 16.625f};
        float iou[3];
#pragma unroll
        for (int k = 0; k < 3; k++) {
            float inter = fminf(aw[k], bw) * fminf(ah[k], bh);
            iou[k] = inter / (aw[k]*ah[k] + 1e-16f + bw*bh - inter);
        }
        int best = 0;
        if (iou[1] > iou[best]) best = 1;
        if (iou[2] > iou[best]) best = 2;

        // ---- elementwise transform ----
        float px   = 1.0f / (1.0f + __expf(-ch[0]));
        float py   = 1.0f / (1.0f + __expf(-ch[1]));
        float pw   = ch[2];
        float ph   = ch[3];
        float conf = 1.0f / (1.0f + __expf(-ch[4]));

        float mx = ch[5];
#pragma unroll
        for (int c = 6; c < NCH; c++) mx = fmaxf(mx, ch[c]);
        float s = 0.0f;
#pragma unroll
        for (int c = 5; c < NCH; c++) { ch[c] = __expf(ch[c] - mx); s += ch[c]; }
        float inv = 1.0f / s;
#pragma unroll
        for (int c = 5; c < NCH; c++) ch[c] *= inv;

        // ---- stage output row in smem ----
        float* srow = &sbuf[tid * SPAD];
        srow[0] = px * 8.0f;
        srow[1] = py * 8.0f;
        srow[2] = pw * 8.0f;
        srow[3] = ph * 8.0f;
        srow[4] = conf;
#pragma unroll
        for (int c = 5; c < NCH; c++) srow[c] = ch[c];

        // ---- loss contributions ----
        bool at_cell = (j == gj) && (i == gi);
        bool is_best = at_cell && (a == best);

        float noobj = 1.0f;
        if (at_cell) {
            if (a == best || iou[a] > 0.5f) noobj = 0.0f;
        }
        if (noobj != 0.0f)
            loss += 100.0f * (-fmaxf(__logf(1.0f - conf), -100.0f));

        if (is_best) {
            float tx = bx - (float)gi;
            float ty = by - (float)gj;
            float tw = __logf(bw / aw[best] + 1e-16f);
            float th = __logf(bh / ah[best] + 1e-16f);
            loss += fabsf(px - tx) + fabsf(py - ty)
                  + fabsf(pw - tw) + fabsf(ph - th);
            loss += -fmaxf(__logf(conf), -100.0f);
#pragma unroll
            for (int c = 0; c < NUM_CLASSES; c++) {
                float p = ch[5 + c];
                if (c == gcls) loss += -fmaxf(__logf(p), -100.0f);
                else           loss += -fmaxf(__logf(1.0f - p), -100.0f);
            }
        }
    }

    __syncthreads();

    // ---- coalesced write: 5120 contiguous floats per block ----
    {
        int ncell = total - base;                 // cells this block owns
        if (ncell > TPB) ncell = TPB;
        int nfl = ncell * NCH;
        size_t gbase = 1 + (size_t)base * NCH;
#pragma unroll
        for (int k = 0; k < NCH; k++) {
            int g = tid + k * TPB;
            if (g < nfl) {
                int cell = g / NCH;
                int c    = g - cell * NCH;
                out[gbase + g] = sbuf[cell * SPAD + c];
            }
        }
    }

    // ---- block reduction -> one double atomic per block ----
    __shared__ float warpsum[TPB / 32];
#pragma unroll
    for (int o = 16; o > 0; o >>= 1)
        loss += __shfl_down_sync(0xffffffffu, loss, o);
    if ((threadIdx.x & 31) == 0) warpsum[threadIdx.x >> 5] = loss;
    __syncthreads();
    if (threadIdx.x < TPB / 32) {
        float v = warpsum[threadIdx.x];
#pragma unroll
        for (int o = (TPB / 64); o > 0; o >>= 1)
            v += __shfl_down_sync(0xffu, v, o);
        if (threadIdx.x == 0)
            atomicAdd(&g_loss, (double)v);
    }
}

// ---------------------------------------------------------------------------
// K3: finalize loss into d_out[0], reset accumulator for next replay
// ---------------------------------------------------------------------------
__global__ void k3_final(float* __restrict__ out) {
    out[0] = (float)g_loss;
    g_loss = 0.0;
}

extern "C" void kernel_launch(void* const* d_in, const int* in_sizes, int n_in,
                              void* d_out, int out_size) {
    const float* x      = (const float*)d_in[0];
    const float* labels = (const float*)d_in[1];
    float* out = (float*)d_out;

    int nB = in_sizes[0] / (NA * NCH * PLANE);
    int total = nB * NA * PLANE;

    k2_main<<<(total + TPB - 1) / TPB, TPB>>>(x, labels, out, nB);
    k3_final<<<1, 1>>>(out);
}